// round 13
// baseline (speedup 1.0000x reference)
#include <cuda_runtime.h>
#include <cuda_fp16.h>
#include <cstdint>

#define N_ROWS 400000
#define C      64
#define KTAPS  27
#define TILE_M 256
#define NTH    128          // 4 warps, each owns a 64x64 output tile
#define NBLK   ((N_ROWS + TILE_M - 1) / TILE_M)   // 1563 (last block: 128 rows)
#define EPS_F  1e-5f

#define STRB   144                        // smem row stride in bytes (72 halves)
#define ABUF_B (TILE_M * STRB)            // 36864 B per A buffer
#define BBUF_B (C * STRB)                 // 9216 B per B buffer
#define BBASE  (2 * ABUF_B)
#define SMEM_BYTES (2 * ABUF_B + 2 * BBUF_B)   // 92160 -> 2 blocks/SM

__device__ float g_sum[C];
__device__ float g_sumsq[C];
__device__ __align__(16) __half g_fh[(size_t)N_ROWS * C];   // fp16 features
__device__ __align__(16) __half g_wh[KTAPS * C * C];        // fp16 W^T [tap][cout][cin]

// ---------------- helpers ----------------
static __device__ __forceinline__ uint32_t smem_u32(const void* p) {
    uint32_t a;
    asm("{ .reg .u64 t; cvta.to.shared.u64 t, %1; cvt.u32.u64 %0, t; }"
        : "=r"(a) : "l"(p));
    return a;
}
static __device__ __forceinline__ uint32_t h2_bits(__half2 h) {
    return *reinterpret_cast<uint32_t*>(&h);
}
static __device__ __forceinline__ void cp16(uint32_t dst, const void* src,
                                            uint32_t src_bytes) {
    asm volatile("cp.async.cg.shared.global [%0], [%1], 16, %2;"
                 :: "r"(dst), "l"(src), "r"(src_bytes) : "memory");
}
#define CP_COMMIT() asm volatile("cp.async.commit_group;" ::: "memory")
#define CP_WAIT(n)  asm volatile("cp.async.wait_group %0;" :: "n"(n) : "memory")

static __device__ __forceinline__ void ldsm_x4(uint32_t& r0, uint32_t& r1,
                                               uint32_t& r2, uint32_t& r3,
                                               uint32_t addr) {
    asm volatile("ldmatrix.sync.aligned.m8n8.x4.shared.b16 {%0,%1,%2,%3}, [%4];"
                 : "=r"(r0), "=r"(r1), "=r"(r2), "=r"(r3) : "r"(addr));
}
static __device__ __forceinline__ void ldsm_x2(uint32_t& r0, uint32_t& r1,
                                               uint32_t addr) {
    asm volatile("ldmatrix.sync.aligned.m8n8.x2.shared.b16 {%0,%1}, [%2];"
                 : "=r"(r0), "=r"(r1) : "r"(addr));
}
static __device__ __forceinline__ void mma_f16(float& c0, float& c1, float& c2, float& c3,
                                               uint32_t a0, uint32_t a1, uint32_t a2, uint32_t a3,
                                               uint32_t b0, uint32_t b1) {
    asm volatile(
        "mma.sync.aligned.m16n8k16.row.col.f32.f16.f16.f32 "
        "{%0,%1,%2,%3}, {%4,%5,%6,%7}, {%8,%9}, {%0,%1,%2,%3};"
        : "+f"(c0), "+f"(c1), "+f"(c2), "+f"(c3)
        : "r"(a0), "r"(a1), "r"(a2), "r"(a3), "r"(b0), "r"(b1));
}

// ---------------- prep kernels ----------------
__global__ __launch_bounds__(256)
void prep_w_kernel(const float* __restrict__ w) {
    int i = blockIdx.x * 256 + threadIdx.x;
    if (i < KTAPS * C * C) {
        int t = i >> 12;             // tap
        int j = (i >> 6) & 63;       // cin
        int n = i & 63;              // cout
        g_wh[(t << 12) + (n << 6) + j] = __float2half_rn(w[i]);
    }
    if (blockIdx.x == 0 && threadIdx.x < C) {
        g_sum[threadIdx.x] = 0.0f; g_sumsq[threadIdx.x] = 0.0f;
    }
}

__global__ __launch_bounds__(256)
void prep_f_kernel(const float4* __restrict__ f) {
    int i = blockIdx.x * 256 + threadIdx.x;
    float4 v0 = f[2 * i];
    float4 v1 = f[2 * i + 1];
    uint4 o;
    o.x = h2_bits(__float22half2_rn(make_float2(v0.x, v0.y)));
    o.y = h2_bits(__float22half2_rn(make_float2(v0.z, v0.w)));
    o.z = h2_bits(__float22half2_rn(make_float2(v1.x, v1.y)));
    o.w = h2_bits(__float22half2_rn(make_float2(v1.z, v1.w)));
    ((uint4*)g_fh)[i] = o;
}

// ---------------- conv kernel ----------------
extern __shared__ __align__(16) char smem[];

__global__ __launch_bounds__(NTH)
void conv_mma_kernel(const int* __restrict__ nmap,
                     float*     __restrict__ out)
{
    const uint32_t sb = smem_u32(smem);
    const int tid  = threadIdx.x;
    const int wid  = tid >> 5;               // 0..3
    const int lane = tid & 31;
    const int grp  = lane >> 2;              // 0..7
    const int tig  = lane & 3;               // 0..3
    const int row0 = blockIdx.x * TILE_M;
    const int rb0  = wid * 64;               // warp's 64-row slab

    const int chunk = tid & 7;               // 16B chunk within a 128B fp16 row
    const int r0t   = tid >> 3;              // 0..15; rows r0t + 16i

    const uint4* feat = (const uint4*)g_fh;  // 8 uint4 per feature row
    const uint4* wgt  = (const uint4*)g_wh;  // 512 uint4 per tap

    float acc[4][8][4];
#pragma unroll
    for (int mt = 0; mt < 4; ++mt)
#pragma unroll
        for (int nt = 0; nt < 8; ++nt)
#pragma unroll
            for (int e = 0; e < 4; ++e) acc[mt][nt][e] = 0.0f;

    int idx_nx[16];

    auto fetch_idx = [&](int k, int* v) {
        const int* nm = nmap + (size_t)k * N_ROWS + row0;
#pragma unroll
        for (int i = 0; i < 16; ++i) {
            const int rr = r0t + i * 16;
            v[i] = (row0 + rr < N_ROWS) ? __ldg(nm + rr) : -1;
        }
    };

    auto issue_tap = [&](int t, int bs, const int* idxv) {
        // B: 512 cp16 over 128 threads = 4 each
        const uint32_t bdst0 = sb + BBASE + bs * BBUF_B;
#pragma unroll
        for (int u = 0; u < 4; ++u) {
            const int idx4 = tid + u * NTH;      // 0..511
            const int j  = idx4 >> 3;            // cout row
            const int c4 = idx4 & 7;
            cp16(bdst0 + j * STRB + c4 * 16, wgt + (t << 9) + idx4, 16);
        }
        // A: 256 rows x 8 chunks = 2048 cp16 over 128 threads = 16 each
        const uint32_t adst0 = sb + bs * ABUF_B;
#pragma unroll
        for (int i = 0; i < 16; ++i) {
            const int rr  = r0t + i * 16;
            const int idx = idxv[i];
            const int safe = idx < 0 ? 0 : idx;
            cp16(adst0 + rr * STRB + chunk * 16,
                 feat + (size_t)safe * 8 + chunk, idx < 0 ? 0u : 16u);
        }
        CP_COMMIT();
    };

    // prologue
    {
        int idx0[16];
        fetch_idx(0, idx0);
        issue_tap(0, 0, idx0);
        fetch_idx(1, idx_nx);
    }

    for (int k = 0; k < KTAPS; ++k) {
        const int s = k & 1;

        if (k + 1 < KTAPS) {
            issue_tap(k + 1, s ^ 1, idx_nx);
            if (k + 2 < KTAPS) fetch_idx(k + 2, idx_nx);
            CP_WAIT(1);
        } else {
            CP_WAIT(0);
        }
        __syncthreads();

        const uint32_t abase = sb + s * ABUF_B;
        const uint32_t bbase = sb + BBASE + s * BBUF_B;

        // ldmatrix lane addressing (constant per thread across ksteps)
        const uint32_t a_lrow = abase + (rb0 + (lane & 15)) * STRB + (lane >> 4) * 16;
        const uint32_t b_lrow = bbase + (lane & 7) * STRB + ((lane >> 3) & 1) * 16;

#pragma unroll
        for (int k0 = 0; k0 < 4; ++k0) {       // 4 k-steps of k16
            const uint32_t kb = k0 * 32;       // 16 halves = 32 B
            uint32_t a[4][4];
#pragma unroll
            for (int mt = 0; mt < 4; ++mt)
                ldsm_x4(a[mt][0], a[mt][1], a[mt][2], a[mt][3],
                        a_lrow + mt * (16 * STRB) + kb);
#pragma unroll
            for (int nt = 0; nt < 8; ++nt) {
                uint32_t b0, b1;
                ldsm_x2(b0, b1, b_lrow + nt * (8 * STRB) + kb);
#pragma unroll
                for (int mt = 0; mt < 4; ++mt)
                    mma_f16(acc[mt][nt][0], acc[mt][nt][1],
                            acc[mt][nt][2], acc[mt][nt][3],
                            a[mt][0], a[mt][1], a[mt][2], a[mt][3], b0, b1);
            }
        }
        __syncthreads();
    }

    // ---- epilogue: store conv output + fused channel stats ----
#pragma unroll
    for (int mt = 0; mt < 4; ++mt) {
        const int r = row0 + rb0 + mt * 16 + grp;
        if (r + 8 < N_ROWS) {
#pragma unroll
            for (int nt = 0; nt < 8; ++nt) {
                const int cpos = nt * 8 + tig * 2;
                *(float2*)(out + (size_t)r * C + cpos) =
                    make_float2(acc[mt][nt][0], acc[mt][nt][1]);
                *(float2*)(out + (size_t)(r + 8) * C + cpos) =
                    make_float2(acc[mt][nt][2], acc[mt][nt][3]);
            }
        } else {
#pragma unroll
            for (int nt = 0; nt < 8; ++nt) {
                const int cpos = nt * 8 + tig * 2;
                if (r < N_ROWS)
                    *(float2*)(out + (size_t)r * C + cpos) =
                        make_float2(acc[mt][nt][0], acc[mt][nt][1]);
                if (r + 8 < N_ROWS)
                    *(float2*)(out + (size_t)(r + 8) * C + cpos) =
                        make_float2(acc[mt][nt][2], acc[mt][nt][3]);
            }
        }
    }

    // stats: phantom rows carry acc==0 (zero-filled A), contribute nothing
#pragma unroll
    for (int nt = 0; nt < 8; ++nt) {
        float s0 = 0.f, s1 = 0.f, q0 = 0.f, q1 = 0.f;
#pragma unroll
        for (int mt = 0; mt < 4; ++mt) {
            s0 += acc[mt][nt][0] + acc[mt][nt][2];
            s1 += acc[mt][nt][1] + acc[mt][nt][3];
            q0 += acc[mt][nt][0] * acc[mt][nt][0] + acc[mt][nt][2] * acc[mt][nt][2];
            q1 += acc[mt][nt][1] * acc[mt][nt][1] + acc[mt][nt][3] * acc[mt][nt][3];
        }
#pragma unroll
        for (int d = 4; d <= 16; d <<= 1) {
            s0 += __shfl_xor_sync(0xFFFFFFFF, s0, d);
            s1 += __shfl_xor_sync(0xFFFFFFFF, s1, d);
            q0 += __shfl_xor_sync(0xFFFFFFFF, q0, d);
            q1 += __shfl_xor_sync(0xFFFFFFFF, q1, d);
        }
        if (lane < 4) {
            const int ch = nt * 8 + lane * 2;
            atomicAdd(&g_sum[ch],     s0);
            atomicAdd(&g_sum[ch + 1], s1);
            atomicAdd(&g_sumsq[ch],     q0);
            atomicAdd(&g_sumsq[ch + 1], q1);
        }
    }
}

__global__ __launch_bounds__(256)
void norm_relu_kernel(float* __restrict__ out,
                      const float* __restrict__ gamma,
                      const float* __restrict__ beta)
{
    __shared__ float sc[C], sh[C];
    int t = threadIdx.x;
    if (t < C) {
        const float invn = 1.0f / (float)N_ROWS;
        float mean = g_sum[t] * invn;
        float var  = g_sumsq[t] * invn - mean * mean;
        float inv  = rsqrtf(var + EPS_F);
        float g    = gamma[t] * inv;
        sc[t] = g;
        sh[t] = beta[t] - mean * g;
    }
    __syncthreads();

    const int total4 = N_ROWS * C / 4;
    float4* o4 = (float4*)out;
    for (int i = blockIdx.x * blockDim.x + t; i < total4;
         i += gridDim.x * blockDim.x) {
        float4 v = o4[i];
        int cb = (i & 15) * 4;
        v.x = fmaxf(fmaf(v.x, sc[cb + 0], sh[cb + 0]), 0.0f);
        v.y = fmaxf(fmaf(v.y, sc[cb + 1], sh[cb + 1]), 0.0f);
        v.z = fmaxf(fmaf(v.z, sc[cb + 2], sh[cb + 2]), 0.0f);
        v.w = fmaxf(fmaf(v.w, sc[cb + 3], sh[cb + 3]), 0.0f);
        o4[i] = v;
    }
}

extern "C" void kernel_launch(void* const* d_in, const int* in_sizes, int n_in,
                              void* d_out, int out_size)
{
    const float* features = (const float*)d_in[0];
    const int*   nmap     = (const int*)  d_in[1];
    const float* weight   = (const float*)d_in[2];
    const float* gamma    = (const float*)d_in[3];
    const float* beta     = (const float*)d_in[4];
    float* out = (float*)d_out;

    cudaFuncSetAttribute(conv_mma_kernel,
                         cudaFuncAttributeMaxDynamicSharedMemorySize, SMEM_BYTES);

    prep_w_kernel<<<(KTAPS * C * C + 255) / 256, 256>>>(weight);
    prep_f_kernel<<<N_ROWS * C / 8 / 256, 256>>>((const float4*)features);
    conv_mma_kernel<<<NBLK, NTH, SMEM_BYTES>>>(nmap, out);
    norm_relu_kernel<<<1184, 256>>>(out, gamma, beta);
}

// round 14
// speedup vs baseline: 1.5197x; 1.5197x over previous
#include <cuda_runtime.h>
#include <cuda_fp16.h>
#include <cstdint>

#define N_ROWS 400000
#define C      64
#define KTAPS  27
#define TILE_M 128
#define NTH    64           // 2 warps, each owns a 64x64 output tile
#define EPS_F  1e-5f

#define STRB   144                        // smem row stride in bytes (72 halves)
#define ABUF_B (TILE_M * STRB)            // 18432 B per A buffer
#define BBUF_B (C * STRB)                 // 9216 B per B buffer
#define BBASE  (2 * ABUF_B)
#define SMEM_BYTES (2 * ABUF_B + 2 * BBUF_B)   // 55296 -> 4 blocks/SM

__device__ float g_sum[C];
__device__ float g_sumsq[C];
__device__ __align__(16) __half g_fh[(size_t)N_ROWS * C];   // fp16 features
__device__ __align__(16) __half g_wh[KTAPS * C * C];        // fp16 W^T [tap][cout][cin]

// ---------------- helpers ----------------
static __device__ __forceinline__ uint32_t smem_u32(const void* p) {
    uint32_t a;
    asm("{ .reg .u64 t; cvta.to.shared.u64 t, %1; cvt.u32.u64 %0, t; }"
        : "=r"(a) : "l"(p));
    return a;
}
static __device__ __forceinline__ uint32_t h2_bits(__half2 h) {
    return *reinterpret_cast<uint32_t*>(&h);
}
static __device__ __forceinline__ void cp16(uint32_t dst, const void* src,
                                            uint32_t src_bytes) {
    asm volatile("cp.async.cg.shared.global [%0], [%1], 16, %2;"
                 :: "r"(dst), "l"(src), "r"(src_bytes) : "memory");
}
#define CP_COMMIT() asm volatile("cp.async.commit_group;" ::: "memory")
#define CP_WAIT(n)  asm volatile("cp.async.wait_group %0;" :: "n"(n) : "memory")

static __device__ __forceinline__ void ldsm_x4(uint32_t& r0, uint32_t& r1,
                                               uint32_t& r2, uint32_t& r3,
                                               uint32_t addr) {
    asm volatile("ldmatrix.sync.aligned.m8n8.x4.shared.b16 {%0,%1,%2,%3}, [%4];"
                 : "=r"(r0), "=r"(r1), "=r"(r2), "=r"(r3) : "r"(addr));
}
static __device__ __forceinline__ void ldsm_x2(uint32_t& r0, uint32_t& r1,
                                               uint32_t addr) {
    asm volatile("ldmatrix.sync.aligned.m8n8.x2.shared.b16 {%0,%1}, [%2];"
                 : "=r"(r0), "=r"(r1) : "r"(addr));
}
static __device__ __forceinline__ void mma_f16(float& c0, float& c1, float& c2, float& c3,
                                               uint32_t a0, uint32_t a1, uint32_t a2, uint32_t a3,
                                               uint32_t b0, uint32_t b1) {
    asm volatile(
        "mma.sync.aligned.m16n8k16.row.col.f32.f16.f16.f32 "
        "{%0,%1,%2,%3}, {%4,%5,%6,%7}, {%8,%9}, {%0,%1,%2,%3};"
        : "+f"(c0), "+f"(c1), "+f"(c2), "+f"(c3)
        : "r"(a0), "r"(a1), "r"(a2), "r"(a3), "r"(b0), "r"(b1));
}

// ---------------- prep kernels ----------------
__global__ __launch_bounds__(256)
void prep_w_kernel(const float* __restrict__ w) {
    int i = blockIdx.x * 256 + threadIdx.x;
    if (i < KTAPS * C * C) {
        int t = i >> 12;             // tap
        int j = (i >> 6) & 63;       // cin
        int n = i & 63;              // cout
        g_wh[(t << 12) + (n << 6) + j] = __float2half_rn(w[i]);
    }
    if (blockIdx.x == 0 && threadIdx.x < C) {
        g_sum[threadIdx.x] = 0.0f; g_sumsq[threadIdx.x] = 0.0f;
    }
}

__global__ __launch_bounds__(256)
void prep_f_kernel(const float4* __restrict__ f) {
    int i = blockIdx.x * 256 + threadIdx.x;
    float4 v0 = f[2 * i];
    float4 v1 = f[2 * i + 1];
    uint4 o;
    o.x = h2_bits(__float22half2_rn(make_float2(v0.x, v0.y)));
    o.y = h2_bits(__float22half2_rn(make_float2(v0.z, v0.w)));
    o.z = h2_bits(__float22half2_rn(make_float2(v1.x, v1.y)));
    o.w = h2_bits(__float22half2_rn(make_float2(v1.z, v1.w)));
    ((uint4*)g_fh)[i] = o;
}

// ---------------- conv kernel ----------------
extern __shared__ __align__(16) char smem[];

__global__ __launch_bounds__(NTH)
void conv_mma_kernel(const int* __restrict__ nmap,
                     float*     __restrict__ out)
{
    const uint32_t sb = smem_u32(smem);
    const int tid  = threadIdx.x;
    const int wid  = tid >> 5;               // 0..1
    const int lane = tid & 31;
    const int grp  = lane >> 2;              // 0..7
    const int tig  = lane & 3;               // 0..3
    const int row0 = blockIdx.x * TILE_M;
    const int rb0  = wid * 64;               // warp's 64-row slab

    const int chunk = tid & 7;               // 16B chunk within a 128B fp16 row
    const int r0t   = tid >> 3;              // 0..7; rows r0t + 8i

    const uint4* feat = (const uint4*)g_fh;  // 8 uint4 per feature row
    const uint4* wgt  = (const uint4*)g_wh;  // 512 uint4 per tap

    float acc[4][8][4];
#pragma unroll
    for (int mt = 0; mt < 4; ++mt)
#pragma unroll
        for (int nt = 0; nt < 8; ++nt)
#pragma unroll
            for (int e = 0; e < 4; ++e) acc[mt][nt][e] = 0.0f;

    int idx_nx[16];

    auto issue_tap = [&](int t, int bs, const int* idxv) {
        // B: 512 cp16 over 64 threads = 8 each
        const uint32_t bdst0 = sb + BBASE + bs * BBUF_B;
#pragma unroll
        for (int u = 0; u < 8; ++u) {
            const int idx4 = tid + u * NTH;      // 0..511
            const int j  = idx4 >> 3;            // cout row
            const int c4 = idx4 & 7;
            cp16(bdst0 + j * STRB + c4 * 16, wgt + (t << 9) + idx4, 16);
        }
        // A: 128 rows x 8 chunks = 1024 cp16 over 64 threads = 16 each
        const uint32_t adst0 = sb + bs * ABUF_B;
#pragma unroll
        for (int i = 0; i < 16; ++i) {
            const int rr  = r0t + i * 8;
            const int idx = idxv[i];
            const int safe = idx < 0 ? 0 : idx;
            cp16(adst0 + rr * STRB + chunk * 16,
                 feat + (size_t)safe * 8 + chunk, idx < 0 ? 0u : 16u);
        }
        CP_COMMIT();
    };

    // prologue
    {
        int idx0[16];
        const int* nm = nmap + row0;
#pragma unroll
        for (int i = 0; i < 16; ++i) idx0[i] = __ldg(nm + r0t + i * 8);
        issue_tap(0, 0, idx0);
        const int* nm1 = nmap + N_ROWS + row0;
#pragma unroll
        for (int i = 0; i < 16; ++i) idx_nx[i] = __ldg(nm1 + r0t + i * 8);
    }

    for (int k = 0; k < KTAPS; ++k) {
        const int s = k & 1;

        if (k + 1 < KTAPS) {
            issue_tap(k + 1, s ^ 1, idx_nx);
            if (k + 2 < KTAPS) {
                const int* nm = nmap + (size_t)(k + 2) * N_ROWS + row0;
#pragma unroll
                for (int i = 0; i < 16; ++i) idx_nx[i] = __ldg(nm + r0t + i * 8);
            }
            CP_WAIT(1);
        } else {
            CP_WAIT(0);
        }
        __syncthreads();

        const uint32_t abase = sb + s * ABUF_B;
        const uint32_t bbase = sb + BBASE + s * BBUF_B;

        // ldmatrix lane addressing (constant per thread across ksteps)
        const uint32_t a_lrow = abase + (rb0 + (lane & 15)) * STRB + (lane >> 4) * 16;
        const uint32_t b_lrow = bbase + (lane & 7) * STRB + ((lane >> 3) & 1) * 16;

#pragma unroll
        for (int k0 = 0; k0 < 4; ++k0) {       // 4 k-steps of k16
            const uint32_t kb = k0 * 32;       // 16 halves = 32 B
            uint32_t a[4][4];
#pragma unroll
            for (int mt = 0; mt < 4; ++mt)
                ldsm_x4(a[mt][0], a[mt][1], a[mt][2], a[mt][3],
                        a_lrow + mt * (16 * STRB) + kb);
#pragma unroll
            for (int nt = 0; nt < 8; ++nt) {
                uint32_t b0, b1;
                ldsm_x2(b0, b1, b_lrow + nt * (8 * STRB) + kb);
#pragma unroll
                for (int mt = 0; mt < 4; ++mt)
                    mma_f16(acc[mt][nt][0], acc[mt][nt][1],
                            acc[mt][nt][2], acc[mt][nt][3],
                            a[mt][0], a[mt][1], a[mt][2], a[mt][3], b0, b1);
            }
        }
        __syncthreads();
    }

    // ---- epilogue: store conv output + fused channel stats ----
#pragma unroll
    for (int mt = 0; mt < 4; ++mt) {
        const int r = row0 + rb0 + mt * 16 + grp;
#pragma unroll
        for (int nt = 0; nt < 8; ++nt) {
            const int cpos = nt * 8 + tig * 2;
            *(float2*)(out + (size_t)r * C + cpos) =
                make_float2(acc[mt][nt][0], acc[mt][nt][1]);
            *(float2*)(out + (size_t)(r + 8) * C + cpos) =
                make_float2(acc[mt][nt][2], acc[mt][nt][3]);
        }
    }

#pragma unroll
    for (int nt = 0; nt < 8; ++nt) {
        float s0 = 0.f, s1 = 0.f, q0 = 0.f, q1 = 0.f;
#pragma unroll
        for (int mt = 0; mt < 4; ++mt) {
            s0 += acc[mt][nt][0] + acc[mt][nt][2];
            s1 += acc[mt][nt][1] + acc[mt][nt][3];
            q0 += acc[mt][nt][0] * acc[mt][nt][0] + acc[mt][nt][2] * acc[mt][nt][2];
            q1 += acc[mt][nt][1] * acc[mt][nt][1] + acc[mt][nt][3] * acc[mt][nt][3];
        }
#pragma unroll
        for (int d = 4; d <= 16; d <<= 1) {
            s0 += __shfl_xor_sync(0xFFFFFFFF, s0, d);
            s1 += __shfl_xor_sync(0xFFFFFFFF, s1, d);
            q0 += __shfl_xor_sync(0xFFFFFFFF, q0, d);
            q1 += __shfl_xor_sync(0xFFFFFFFF, q1, d);
        }
        if (lane < 4) {
            const int ch = nt * 8 + lane * 2;
            atomicAdd(&g_sum[ch],     s0);
            atomicAdd(&g_sum[ch + 1], s1);
            atomicAdd(&g_sumsq[ch],     q0);
            atomicAdd(&g_sumsq[ch + 1], q1);
        }
    }
}

__global__ __launch_bounds__(256)
void norm_relu_kernel(float* __restrict__ out,
                      const float* __restrict__ gamma,
                      const float* __restrict__ beta)
{
    __shared__ float sc[C], sh[C];
    int t = threadIdx.x;
    if (t < C) {
        const float invn = 1.0f / (float)N_ROWS;
        float mean = g_sum[t] * invn;
        float var  = g_sumsq[t] * invn - mean * mean;
        float inv  = rsqrtf(var + EPS_F);
        float g    = gamma[t] * inv;
        sc[t] = g;
        sh[t] = beta[t] - mean * g;
    }
    __syncthreads();

    const int total4 = N_ROWS * C / 4;
    float4* o4 = (float4*)out;
    for (int i = blockIdx.x * blockDim.x + t; i < total4;
         i += gridDim.x * blockDim.x) {
        float4 v = o4[i];
        int cb = (i & 15) * 4;
        v.x = fmaxf(fmaf(v.x, sc[cb + 0], sh[cb + 0]), 0.0f);
        v.y = fmaxf(fmaf(v.y, sc[cb + 1], sh[cb + 1]), 0.0f);
        v.z = fmaxf(fmaf(v.z, sc[cb + 2], sh[cb + 2]), 0.0f);
        v.w = fmaxf(fmaf(v.w, sc[cb + 3], sh[cb + 3]), 0.0f);
        o4[i] = v;
    }
}

extern "C" void kernel_launch(void* const* d_in, const int* in_sizes, int n_in,
                              void* d_out, int out_size)
{
    const float* features = (const float*)d_in[0];
    const int*   nmap     = (const int*)  d_in[1];
    const float* weight   = (const float*)d_in[2];
    const float* gamma    = (const float*)d_in[3];
    const float* beta     = (const float*)d_in[4];
    float* out = (float*)d_out;

    cudaFuncSetAttribute(conv_mma_kernel,
                         cudaFuncAttributeMaxDynamicSharedMemorySize, SMEM_BYTES);

    prep_w_kernel<<<(KTAPS * C * C + 255) / 256, 256>>>(weight);
    prep_f_kernel<<<N_ROWS * C / 8 / 256, 256>>>((const float4*)features);
    conv_mma_kernel<<<N_ROWS / TILE_M, NTH, SMEM_BYTES>>>(nmap, out);
    norm_relu_kernel<<<1184, 256>>>(out, gamma, beta);
}